// round 1
// baseline (speedup 1.0000x reference)
#include <cuda_runtime.h>
#include <math.h>

#define B_   2
#define S_   2048
#define D_   1024
#define H_   16
#define DK_  64
#define DFF_ 4096
#define M_   (B_ * S_)      // 4096 rows
#define EPS_ 1e-6f

// ---------------- scratch (device globals; no allocation allowed) ----------------
__device__ float g_h  [(size_t)M_ * D_];    // LN output (reused for LN2)
__device__ float g_q  [(size_t)M_ * D_];    // (b,h,s,d) layout
__device__ float g_k  [(size_t)M_ * D_];
__device__ float g_v  [(size_t)M_ * D_];
__device__ float g_ctx[(size_t)M_ * D_];    // (m, h*DK+d) layout
__device__ float g_x2 [(size_t)M_ * D_];    // residual-1 output
__device__ float g_ff [(size_t)M_ * DFF_];  // relu(h2@W1+b1)

// ---------------- layernorm: alpha*(x-mean)/(std+eps)+beta, std unbiased ----------
__global__ void layernorm_kernel(const float* __restrict__ x,
                                 const float* __restrict__ alpha,
                                 const float* __restrict__ beta,
                                 float* __restrict__ out) {
    int row = blockIdx.x;
    int t = threadIdx.x;                       // 256 threads, 4 elems each (D=1024)
    const float4* xr = (const float4*)(x + (size_t)row * D_);
    float4 v = xr[t];
    float s  = v.x + v.y + v.z + v.w;
    float sq = v.x*v.x + v.y*v.y + v.z*v.z + v.w*v.w;
    #pragma unroll
    for (int o = 16; o > 0; o >>= 1) {
        s  += __shfl_xor_sync(0xFFFFFFFFu, s,  o);
        sq += __shfl_xor_sync(0xFFFFFFFFu, sq, o);
    }
    __shared__ float ss[8], sqs[8];
    __shared__ float mean_sh, inv_sh;
    int w = t >> 5;
    if ((t & 31) == 0) { ss[w] = s; sqs[w] = sq; }
    __syncthreads();
    if (t == 0) {
        float S = 0.f, SQ = 0.f;
        #pragma unroll
        for (int i = 0; i < 8; i++) { S += ss[i]; SQ += sqs[i]; }
        float mean = S / (float)D_;
        float var  = (SQ - (float)D_ * mean * mean) / (float)(D_ - 1);
        float sd   = sqrtf(fmaxf(var, 0.f));
        mean_sh = mean;
        inv_sh  = 1.f / (sd + EPS_);
    }
    __syncthreads();
    float a = alpha[0], g = beta[0];
    float mean = mean_sh, inv = inv_sh;
    float4 o4;
    o4.x = a * (v.x - mean) * inv + g;
    o4.y = a * (v.y - mean) * inv + g;
    o4.z = a * (v.z - mean) * inv + g;
    o4.w = a * (v.w - mean) * inv + g;
    ((float4*)(out + (size_t)row * D_))[t] = o4;
}

// ---------------- tiled SGEMM: C = A(MxK) @ B(KxN) + bias, epilogues --------------
// EPI: 0 = bias, 1 = bias+relu, 2 = bias+residual add, 3 = bias + QKV permute store
template<int EPI>
__global__ void sgemm_kernel(const float* __restrict__ A,
                             const float* __restrict__ Bm,
                             const float* __restrict__ bias,
                             const float* __restrict__ res,
                             float* __restrict__ C,
                             int Mdim, int Ndim, int Kdim) {
    __shared__ float As[8][128];   // A^T tile
    __shared__ float Bs[8][128];

    int bx = blockIdx.x, by = blockIdx.y;
    int tid = threadIdx.x;
    int tx = tid & 15, ty = tid >> 4;

    float acc[8][8];
    #pragma unroll
    for (int i = 0; i < 8; i++)
        #pragma unroll
        for (int j = 0; j < 8; j++) acc[i][j] = 0.f;

    int aRow  = by * 128 + (tid >> 1);
    int aHalf = (tid & 1) * 4;
    int bRow  = tid >> 5;
    int bCol  = (tid & 31) * 4;

    const float* Aptr = A + (size_t)aRow * Kdim + aHalf;
    const float* Bptr = Bm + (size_t)bRow * Ndim + bx * 128 + bCol;

    for (int k0 = 0; k0 < Kdim; k0 += 8) {
        float4 av = *(const float4*)(Aptr + k0);
        float4 bv = *(const float4*)(Bptr + (size_t)k0 * Ndim);
        __syncthreads();
        As[aHalf + 0][tid >> 1] = av.x;
        As[aHalf + 1][tid >> 1] = av.y;
        As[aHalf + 2][tid >> 1] = av.z;
        As[aHalf + 3][tid >> 1] = av.w;
        *(float4*)&Bs[bRow][bCol] = bv;
        __syncthreads();
        #pragma unroll
        for (int kk = 0; kk < 8; kk++) {
            float a[8], b[8];
            #pragma unroll
            for (int i = 0; i < 8; i++) a[i] = As[kk][ty * 8 + i];
            #pragma unroll
            for (int j = 0; j < 8; j++) b[j] = Bs[kk][tx * 8 + j];
            #pragma unroll
            for (int i = 0; i < 8; i++)
                #pragma unroll
                for (int j = 0; j < 8; j++)
                    acc[i][j] = fmaf(a[i], b[j], acc[i][j]);
        }
    }

    int row0 = by * 128 + ty * 8;
    int col0 = bx * 128 + tx * 8;
    #pragma unroll
    for (int i = 0; i < 8; i++) {
        int row = row0 + i;
        #pragma unroll
        for (int j = 0; j < 8; j++) {
            int col = col0 + j;
            float val = acc[i][j] + bias[col];
            if (EPI == 1) val = fmaxf(val, 0.f);
            if (EPI == 2) val += res[(size_t)row * Ndim + col];
            if (EPI == 3) {
                int bb = row / S_, s = row % S_;
                int hh = col >> 6, dd = col & 63;
                C[((((size_t)bb * H_ + hh) * S_) + s) * DK_ + dd] = val;
            } else {
                C[(size_t)row * Ndim + col] = val;
            }
        }
    }
}

// ---------------- flash attention (fp32, no mask) ---------------------------------
// grid: (S/128 q-tiles, B*H), block: 256 threads. KV tile = 64.
#define FA_QS(d, i)  smQ[(d) * 128 + (i)]
#define FA_KS(d, j)  smK[(d) * 64 + (j)]
#define FA_VS(j, d)  smV[(j) * 64 + (d)]
#define FA_PS(j, i)  smP[(j) * 129 + (i)]
#define FA_SMEM_FLOATS (64*128 + 64*64 + 64*64 + 64*129 + 3*128)

__global__ void flash_attn_kernel(const float* __restrict__ Q,
                                  const float* __restrict__ K,
                                  const float* __restrict__ V,
                                  float* __restrict__ ctx) {
    extern __shared__ float sm[];
    float* smQ = sm;                    // [64][128]  Q^T (pre-scaled)
    float* smK = smQ + 64 * 128;        // [64][64]   K^T
    float* smV = smK + 64 * 64;         // [64][64]   V
    float* smP = smV + 64 * 64;         // [64][129]  scores^T / probs^T (padded)
    float* m_s  = smP + 64 * 129;       // [128]
    float* l_s  = m_s + 128;            // [128]
    float* rf_s = l_s + 128;            // [128]

    int tid = threadIdx.x;
    int tx = tid & 15, ty = tid >> 4;   // 16 x 16 thread grid
    int bh = blockIdx.y;                // b*H + h
    int qt = blockIdx.x;

    const float* Qp = Q + ((size_t)bh * S_ + qt * 128) * DK_;
    const float* Kp = K + (size_t)bh * S_ * DK_;
    const float* Vp = V + (size_t)bh * S_ * DK_;

    // Q tile: 128 rows x 64 cols, scaled by 1/sqrt(dk)=0.125, transposed
    for (int idx = tid; idx < 128 * 16; idx += 256) {
        int r = idx >> 4, c4 = (idx & 15) * 4;
        float4 v = *(const float4*)(Qp + (size_t)r * DK_ + c4);
        FA_QS(c4 + 0, r) = v.x * 0.125f;
        FA_QS(c4 + 1, r) = v.y * 0.125f;
        FA_QS(c4 + 2, r) = v.z * 0.125f;
        FA_QS(c4 + 3, r) = v.w * 0.125f;
    }
    if (tid < 128) { m_s[tid] = -1e30f; l_s[tid] = 0.f; }

    float oacc[8][4];
    #pragma unroll
    for (int i = 0; i < 8; i++)
        #pragma unroll
        for (int j = 0; j < 4; j++) oacc[i][j] = 0.f;

    for (int kt = 0; kt < S_ / 64; kt++) {
        __syncthreads();   // previous iteration fully consumed smK/smV/smP (and Q load done)
        const float* Kt = Kp + (size_t)kt * 64 * DK_;
        const float* Vt = Vp + (size_t)kt * 64 * DK_;
        for (int idx = tid; idx < 64 * 16; idx += 256) {
            int r = idx >> 4, c4 = (idx & 15) * 4;
            float4 kv = *(const float4*)(Kt + (size_t)r * DK_ + c4);
            FA_KS(c4 + 0, r) = kv.x;
            FA_KS(c4 + 1, r) = kv.y;
            FA_KS(c4 + 2, r) = kv.z;
            FA_KS(c4 + 3, r) = kv.w;
            float4 vv = *(const float4*)(Vt + (size_t)r * DK_ + c4);
            *(float4*)&FA_VS(r, c4) = vv;
        }
        __syncthreads();

        // scores: s[i][j] = sum_d Qs[d][i] * Ks[d][j]
        float sacc[8][4];
        #pragma unroll
        for (int i = 0; i < 8; i++)
            #pragma unroll
            for (int j = 0; j < 4; j++) sacc[i][j] = 0.f;
        #pragma unroll 4
        for (int d = 0; d < DK_; d++) {
            float a[8], b[4];
            #pragma unroll
            for (int i = 0; i < 8; i++) a[i] = FA_QS(d, ty * 8 + i);
            #pragma unroll
            for (int j = 0; j < 4; j++) b[j] = FA_KS(d, tx * 4 + j);
            #pragma unroll
            for (int i = 0; i < 8; i++)
                #pragma unroll
                for (int j = 0; j < 4; j++)
                    sacc[i][j] = fmaf(a[i], b[j], sacc[i][j]);
        }
        #pragma unroll
        for (int i = 0; i < 8; i++)
            #pragma unroll
            for (int j = 0; j < 4; j++)
                FA_PS(tx * 4 + j, ty * 8 + i) = sacc[i][j];
        __syncthreads();

        // online softmax per row (128 threads, one row each)
        if (tid < 128) {
            int r = tid;
            float mold = m_s[r];
            float mx = mold;
            #pragma unroll 8
            for (int j = 0; j < 64; j++) mx = fmaxf(mx, FA_PS(j, r));
            float sum = 0.f;
            #pragma unroll 8
            for (int j = 0; j < 64; j++) {
                float p = expf(FA_PS(j, r) - mx);
                FA_PS(j, r) = p;
                sum += p;
            }
            float rf = expf(mold - mx);     // 0 on first tile (mold=-1e30)
            m_s[r]  = mx;
            l_s[r]  = l_s[r] * rf + sum;
            rf_s[r] = rf;
        }
        __syncthreads();

        // rescale + O += P @ V
        float rf[8];
        #pragma unroll
        for (int i = 0; i < 8; i++) rf[i] = rf_s[ty * 8 + i];
        #pragma unroll
        for (int i = 0; i < 8; i++)
            #pragma unroll
            for (int j = 0; j < 4; j++) oacc[i][j] *= rf[i];
        #pragma unroll 4
        for (int j = 0; j < 64; j++) {
            float a[8], b[4];
            #pragma unroll
            for (int i = 0; i < 8; i++) a[i] = FA_PS(j, ty * 8 + i);
            #pragma unroll
            for (int c = 0; c < 4; c++) b[c] = FA_VS(j, tx * 4 + c);
            #pragma unroll
            for (int i = 0; i < 8; i++)
                #pragma unroll
                for (int c = 0; c < 4; c++)
                    oacc[i][c] = fmaf(a[i], b[c], oacc[i][c]);
        }
    }

    // write ctx in (m, h*DK+d) layout
    int b = bh / H_, h = bh % H_;
    #pragma unroll
    for (int i = 0; i < 8; i++) {
        int s = qt * 128 + ty * 8 + i;
        float inv = 1.f / l_s[ty * 8 + i];
        #pragma unroll
        for (int j = 0; j < 4; j++) {
            ctx[(size_t)(b * S_ + s) * D_ + h * DK_ + tx * 4 + j] = oacc[i][j] * inv;
        }
    }
}

// ---------------- launch ----------------------------------------------------------
extern "C" void kernel_launch(void* const* d_in, const int* in_sizes, int n_in,
                              void* d_out, int out_size) {
    const float* x  = (const float*)d_in[0];
    // d_in[1] = src_mask (no-op in reference, ignored)
    const float* Wq = (const float*)d_in[2];
    const float* bq = (const float*)d_in[3];
    const float* Wk = (const float*)d_in[4];
    const float* bk = (const float*)d_in[5];
    const float* Wv = (const float*)d_in[6];
    const float* bv = (const float*)d_in[7];
    const float* Wo = (const float*)d_in[8];
    const float* bo = (const float*)d_in[9];
    const float* W1 = (const float*)d_in[10];
    const float* b1 = (const float*)d_in[11];
    const float* W2 = (const float*)d_in[12];
    const float* b2 = (const float*)d_in[13];
    const float* a1 = (const float*)d_in[14];
    const float* g1 = (const float*)d_in[15];
    const float* a2 = (const float*)d_in[16];
    const float* g2 = (const float*)d_in[17];
    float* out = (float*)d_out;

    float *hbuf, *qb, *kb, *vb, *ctx, *x2, *ffb;
    cudaGetSymbolAddress((void**)&hbuf, g_h);
    cudaGetSymbolAddress((void**)&qb,   g_q);
    cudaGetSymbolAddress((void**)&kb,   g_k);
    cudaGetSymbolAddress((void**)&vb,   g_v);
    cudaGetSymbolAddress((void**)&ctx,  g_ctx);
    cudaGetSymbolAddress((void**)&x2,   g_x2);
    cudaGetSymbolAddress((void**)&ffb,  g_ff);

    const int FA_SMEM = FA_SMEM_FLOATS * (int)sizeof(float);
    cudaFuncSetAttribute(flash_attn_kernel,
                         cudaFuncAttributeMaxDynamicSharedMemorySize, FA_SMEM);

    dim3 gD(D_ / 128, M_ / 128);     // (8, 32)
    dim3 gF(DFF_ / 128, M_ / 128);   // (32, 32)

    // 1. LN1
    layernorm_kernel<<<M_, 256>>>(x, a1, g1, hbuf);
    // 2. QKV projections (permuted store into (b,h,s,d))
    sgemm_kernel<3><<<gD, 256>>>(hbuf, Wq, bq, nullptr, qb, M_, D_, D_);
    sgemm_kernel<3><<<gD, 256>>>(hbuf, Wk, bk, nullptr, kb, M_, D_, D_);
    sgemm_kernel<3><<<gD, 256>>>(hbuf, Wv, bv, nullptr, vb, M_, D_, D_);
    // 3. attention
    flash_attn_kernel<<<dim3(S_ / 128, B_ * H_), 256, FA_SMEM>>>(qb, kb, vb, ctx);
    // 4. O projection + residual 1
    sgemm_kernel<2><<<gD, 256>>>(ctx, Wo, bo, x, x2, M_, D_, D_);
    // 5. LN2
    layernorm_kernel<<<M_, 256>>>(x2, a2, g2, hbuf);
    // 6. FFN up + ReLU
    sgemm_kernel<1><<<gF, 256>>>(hbuf, W1, b1, nullptr, ffb, M_, DFF_, D_);
    // 7. FFN down + residual 2 -> output
    sgemm_kernel<2><<<gD, 256>>>(ffb, W2, b2, x2, out, M_, D_, DFF_);
}

// round 3
// speedup vs baseline: 1.9994x; 1.9994x over previous
#include <cuda_runtime.h>
#include <cstdint>
#include <stdint.h>
#include <math.h>

#define B_   2
#define S_   2048
#define D_   1024
#define H_   16
#define DK_  64
#define DFF_ 4096
#define M_   (B_ * S_)      // 4096 rows
#define EPS_ 1e-6f

// ---------------- scratch (device globals; no allocation allowed) ----------------
__device__ float g_h  [(size_t)M_ * D_];    // LN output (reused for LN2)
__device__ float g_q  [(size_t)M_ * D_];    // (b,h,s,d) layout
__device__ float g_k  [(size_t)M_ * D_];
__device__ float g_v  [(size_t)M_ * D_];
__device__ float g_ctx[(size_t)M_ * D_];    // (m, h*DK+d) layout
__device__ float g_x2 [(size_t)M_ * D_];    // residual-1 output
__device__ float g_ff [(size_t)M_ * DFF_];  // relu(h2@W1+b1)

// ---------------- layernorm: alpha*(x-mean)/(std+eps)+beta, std unbiased ----------
__global__ void layernorm_kernel(const float* __restrict__ x,
                                 const float* __restrict__ alpha,
                                 const float* __restrict__ beta,
                                 float* __restrict__ out) {
    int row = blockIdx.x;
    int t = threadIdx.x;                       // 256 threads, 4 elems each (D=1024)
    const float4* xr = (const float4*)(x + (size_t)row * D_);
    float4 v = xr[t];
    float s  = v.x + v.y + v.z + v.w;
    float sq = v.x*v.x + v.y*v.y + v.z*v.z + v.w*v.w;
    #pragma unroll
    for (int o = 16; o > 0; o >>= 1) {
        s  += __shfl_xor_sync(0xFFFFFFFFu, s,  o);
        sq += __shfl_xor_sync(0xFFFFFFFFu, sq, o);
    }
    __shared__ float ss[8], sqs[8];
    __shared__ float mean_sh, inv_sh;
    int w = t >> 5;
    if ((t & 31) == 0) { ss[w] = s; sqs[w] = sq; }
    __syncthreads();
    if (t == 0) {
        float S = 0.f, SQ = 0.f;
        #pragma unroll
        for (int i = 0; i < 8; i++) { S += ss[i]; SQ += sqs[i]; }
        float mean = S / (float)D_;
        float var  = (SQ - (float)D_ * mean * mean) / (float)(D_ - 1);
        float sd   = sqrtf(fmaxf(var, 0.f));
        mean_sh = mean;
        inv_sh  = 1.f / (sd + EPS_);
    }
    __syncthreads();
    float a = alpha[0], g = beta[0];
    float mean = mean_sh, inv = inv_sh;
    float4 o4;
    o4.x = a * (v.x - mean) * inv + g;
    o4.y = a * (v.y - mean) * inv + g;
    o4.z = a * (v.z - mean) * inv + g;
    o4.w = a * (v.w - mean) * inv + g;
    ((float4*)(out + (size_t)row * D_))[t] = o4;
}

// ======================= TF32 tensor-core GEMM ===================================
// C = A(MxK) @ B(KxN) + bias, epilogues:
// EPI: 0 = bias, 1 = bias+relu, 2 = bias+residual add, 3 = bias + QKV permute store
// Block tile 128x128, BK=32, 8 warps (each 32x64), 3-stage cp.async pipeline.
// A smem stride 36 floats, B smem stride 132 floats -> conflict-free frag loads.

#define GBM 128
#define GBN 128
#define GBK 32
#define G_ASTRIDE 36
#define G_BSTRIDE 132
#define G_ASZ (GBM * G_ASTRIDE)      // 4608 floats
#define G_BSZ (GBK * G_BSTRIDE)      // 4224 floats
#define G_STG (G_ASZ + G_BSZ)        // 8832 floats per stage
#define G_STAGES 3
#define G_SMEM_BYTES (G_STAGES * G_STG * 4)  // 105984 B

__device__ __forceinline__ uint32_t f2tf32(float f) {
    uint32_t u;
    asm("cvt.rna.tf32.f32 %0, %1;" : "=r"(u) : "f"(f));
    return u;
}

__device__ __forceinline__ void mma_tf32(float c[4], const uint32_t a[4],
                                         uint32_t b0, uint32_t b1) {
    asm volatile(
        "mma.sync.aligned.m16n8k8.row.col.f32.tf32.tf32.f32 "
        "{%0,%1,%2,%3}, {%4,%5,%6,%7}, {%8,%9}, {%0,%1,%2,%3};"
        : "+f"(c[0]), "+f"(c[1]), "+f"(c[2]), "+f"(c[3])
        : "r"(a[0]), "r"(a[1]), "r"(a[2]), "r"(a[3]), "r"(b0), "r"(b1));
}

__device__ __forceinline__ void cp16(void* smem_dst, const void* gsrc) {
    uint32_t s = (uint32_t)__cvta_generic_to_shared(smem_dst);
    asm volatile("cp.async.cg.shared.global [%0], [%1], 16;\n" :: "r"(s), "l"(gsrc));
}

template<int EPI>
__global__ void __launch_bounds__(256)
gemm_tf32(const float* __restrict__ A,
          const float* __restrict__ Bm,
          const float* __restrict__ bias,
          const float* __restrict__ res,
          float* __restrict__ C,
          int Mdim, int Ndim, int Kdim) {
    extern __shared__ float sm[];

    int bx = blockIdx.x, by = blockIdx.y;
    int t = threadIdx.x;
    int lane = t & 31, warp = t >> 5;
    int wm = warp >> 1;                // 0..3 -> 32-row strips
    int wn = warp & 1;                 // 0..1 -> 64-col strips
    int gid = lane >> 2, tig = lane & 3;

    const int nk = Kdim / GBK;

    // prefetch one stage: A tile [128][32] from (by*128, k0), B tile [32][128]
    auto prefetch = [&](int stage, int k0) {
        float* base = sm + stage * G_STG;
        #pragma unroll
        for (int i = 0; i < 4; i++) {
            int lin = t + i * 256;                     // 0..1023
            int m = lin >> 3, ch = lin & 7;            // 8 x 16B chunks per A row
            cp16(base + m * G_ASTRIDE + ch * 4,
                 A + (size_t)(by * GBM + m) * Kdim + k0 + ch * 4);
        }
        float* bbase = base + G_ASZ;
        #pragma unroll
        for (int i = 0; i < 4; i++) {
            int lin = t + i * 256;
            int r = lin >> 5, ch = lin & 31;           // 32 x 16B chunks per B row
            cp16(bbase + r * G_BSTRIDE + ch * 4,
                 Bm + (size_t)(k0 + r) * Ndim + bx * GBN + ch * 4);
        }
    };

    float acc[2][8][4];
    #pragma unroll
    for (int mt = 0; mt < 2; mt++)
        #pragma unroll
        for (int nt = 0; nt < 8; nt++)
            #pragma unroll
            for (int c = 0; c < 4; c++) acc[mt][nt][c] = 0.f;

    #pragma unroll
    for (int s = 0; s < G_STAGES; s++) {
        prefetch(s, s * GBK);
        asm volatile("cp.async.commit_group;" ::: "memory");
    }

    for (int kt = 0; kt < nk; kt++) {
        asm volatile("cp.async.wait_group 2;" ::: "memory");
        __syncthreads();

        const float* pA = sm + (kt % G_STAGES) * G_STG;
        const float* pB = pA + G_ASZ;

        #pragma unroll
        for (int k8 = 0; k8 < 4; k8++) {
            uint32_t a[2][4];
            #pragma unroll
            for (int mt = 0; mt < 2; mt++) {
                int r0 = wm * 32 + mt * 16;
                int kc = k8 * 8 + tig;
                a[mt][0] = f2tf32(pA[(r0 + gid    ) * G_ASTRIDE + kc    ]);
                a[mt][1] = f2tf32(pA[(r0 + gid + 8) * G_ASTRIDE + kc    ]);
                a[mt][2] = f2tf32(pA[(r0 + gid    ) * G_ASTRIDE + kc + 4]);
                a[mt][3] = f2tf32(pA[(r0 + gid + 8) * G_ASTRIDE + kc + 4]);
            }
            #pragma unroll
            for (int nt = 0; nt < 8; nt++) {
                int n0 = wn * 64 + nt * 8;
                uint32_t b0 = f2tf32(pB[(k8 * 8 + tig    ) * G_BSTRIDE + n0 + gid]);
                uint32_t b1 = f2tf32(pB[(k8 * 8 + tig + 4) * G_BSTRIDE + n0 + gid]);
                mma_tf32(acc[0][nt], a[0], b0, b1);
                mma_tf32(acc[1][nt], a[1], b0, b1);
            }
        }

        __syncthreads();
        if (kt + G_STAGES < nk) prefetch((kt % G_STAGES), (kt + G_STAGES) * GBK);
        asm volatile("cp.async.commit_group;" ::: "memory");
    }

    // epilogue
    auto store2 = [&](int row, int col, float vx, float vy) {
        vx += bias[col];
        vy += bias[col + 1];
        if (EPI == 1) { vx = fmaxf(vx, 0.f); vy = fmaxf(vy, 0.f); }
        if (EPI == 2) {
            float2 r = *(const float2*)(res + (size_t)row * Ndim + col);
            vx += r.x; vy += r.y;
        }
        if (EPI == 3) {
            int bb = row / S_, s = row % S_;
            int hh = col >> 6, dd = col & 63;
            float2* p = (float2*)(C + ((((size_t)bb * H_ + hh) * S_) + s) * DK_ + dd);
            *p = make_float2(vx, vy);
        } else {
            *(float2*)(C + (size_t)row * Ndim + col) = make_float2(vx, vy);
        }
    };

    #pragma unroll
    for (int mt = 0; mt < 2; mt++) {
        #pragma unroll
        for (int nt = 0; nt < 8; nt++) {
            int row = by * GBM + wm * 32 + mt * 16 + gid;
            int col = bx * GBN + wn * 64 + nt * 8 + tig * 2;
            store2(row,     col, acc[mt][nt][0], acc[mt][nt][1]);
            store2(row + 8, col, acc[mt][nt][2], acc[mt][nt][3]);
        }
    }
}

// ---------------- flash attention (fp32, no mask) ---------------------------------
// grid: (S/128 q-tiles, B*H), block: 256 threads. KV tile = 64.
#define FA_QS(d, i)  smQ[(d) * 128 + (i)]
#define FA_KS(d, j)  smK[(d) * 64 + (j)]
#define FA_VS(j, d)  smV[(j) * 64 + (d)]
#define FA_PS(j, i)  smP[(j) * 129 + (i)]
#define FA_SMEM_FLOATS (64*128 + 64*64 + 64*64 + 64*129 + 3*128)

__global__ void flash_attn_kernel(const float* __restrict__ Q,
                                  const float* __restrict__ K,
                                  const float* __restrict__ V,
                                  float* __restrict__ ctx) {
    extern __shared__ float sm[];
    float* smQ = sm;                    // [64][128]  Q^T (pre-scaled)
    float* smK = smQ + 64 * 128;        // [64][64]   K^T
    float* smV = smK + 64 * 64;         // [64][64]   V
    float* smP = smV + 64 * 64;         // [64][129]  scores^T / probs^T (padded)
    float* m_s  = smP + 64 * 129;       // [128]
    float* l_s  = m_s + 128;            // [128]
    float* rf_s = l_s + 128;            // [128]

    int tid = threadIdx.x;
    int tx = tid & 15, ty = tid >> 4;   // 16 x 16 thread grid
    int bh = blockIdx.y;                // b*H + h
    int qt = blockIdx.x;

    const float* Qp = Q + ((size_t)bh * S_ + qt * 128) * DK_;
    const float* Kp = K + (size_t)bh * S_ * DK_;
    const float* Vp = V + (size_t)bh * S_ * DK_;

    for (int idx = tid; idx < 128 * 16; idx += 256) {
        int r = idx >> 4, c4 = (idx & 15) * 4;
        float4 v = *(const float4*)(Qp + (size_t)r * DK_ + c4);
        FA_QS(c4 + 0, r) = v.x * 0.125f;
        FA_QS(c4 + 1, r) = v.y * 0.125f;
        FA_QS(c4 + 2, r) = v.z * 0.125f;
        FA_QS(c4 + 3, r) = v.w * 0.125f;
    }
    if (tid < 128) { m_s[tid] = -1e30f; l_s[tid] = 0.f; }

    float oacc[8][4];
    #pragma unroll
    for (int i = 0; i < 8; i++)
        #pragma unroll
        for (int j = 0; j < 4; j++) oacc[i][j] = 0.f;

    for (int kt = 0; kt < S_ / 64; kt++) {
        __syncthreads();
        const float* Kt = Kp + (size_t)kt * 64 * DK_;
        const float* Vt = Vp + (size_t)kt * 64 * DK_;
        for (int idx = tid; idx < 64 * 16; idx += 256) {
            int r = idx >> 4, c4 = (idx & 15) * 4;
            float4 kv = *(const float4*)(Kt + (size_t)r * DK_ + c4);
            FA_KS(c4 + 0, r) = kv.x;
            FA_KS(c4 + 1, r) = kv.y;
            FA_KS(c4 + 2, r) = kv.z;
            FA_KS(c4 + 3, r) = kv.w;
            float4 vv = *(const float4*)(Vt + (size_t)r * DK_ + c4);
            *(float4*)&FA_VS(r, c4) = vv;
        }
        __syncthreads();

        float sacc[8][4];
        #pragma unroll
        for (int i = 0; i < 8; i++)
            #pragma unroll
            for (int j = 0; j < 4; j++) sacc[i][j] = 0.f;
        #pragma unroll 4
        for (int d = 0; d < DK_; d++) {
            float a[8], b[4];
            #pragma unroll
            for (int i = 0; i < 8; i++) a[i] = FA_QS(d, ty * 8 + i);
            #pragma unroll
            for (int j = 0; j < 4; j++) b[j] = FA_KS(d, tx * 4 + j);
            #pragma unroll
            for (int i = 0; i < 8; i++)
                #pragma unroll
                for (int j = 0; j < 4; j++)
                    sacc[i][j] = fmaf(a[i], b[j], sacc[i][j]);
        }
        #pragma unroll
        for (int i = 0; i < 8; i++)
            #pragma unroll
            for (int j = 0; j < 4; j++)
                FA_PS(tx * 4 + j, ty * 8 + i) = sacc[i][j];
        __syncthreads();

        if (tid < 128) {
            int r = tid;
            float mold = m_s[r];
            float mx = mold;
            #pragma unroll 8
            for (int j = 0; j < 64; j++) mx = fmaxf(mx, FA_PS(j, r));
            float sum = 0.f;
            #pragma unroll 8
            for (int j = 0; j < 64; j++) {
                float p = expf(FA_PS(j, r) - mx);
                FA_PS(j, r) = p;
                sum += p;
            }
            float rf = expf(mold - mx);
            m_s[r]  = mx;
            l_s[r]  = l_s[r] * rf + sum;
            rf_s[r] = rf;
        }
        __syncthreads();

        float rf[8];
        #pragma unroll
        for (int i = 0; i < 8; i++) rf[i] = rf_s[ty * 8 + i];
        #pragma unroll
        for (int i = 0; i < 8; i++)
            #pragma unroll
            for (int j = 0; j < 4; j++) oacc[i][j] *= rf[i];
        #pragma unroll 4
        for (int j = 0; j < 64; j++) {
            float a[8], b[4];
            #pragma unroll
            for (int i = 0; i < 8; i++) a[i] = FA_PS(j, ty * 8 + i);
            #pragma unroll
            for (int c = 0; c < 4; c++) b[c] = FA_VS(j, tx * 4 + c);
            #pragma unroll
            for (int i = 0; i < 8; i++)
                #pragma unroll
                for (int c = 0; c < 4; c++)
                    oacc[i][c] = fmaf(a[i], b[c], oacc[i][c]);
        }
    }

    int b = bh / H_, h = bh % H_;
    #pragma unroll
    for (int i = 0; i < 8; i++) {
        int s = qt * 128 + ty * 8 + i;
        float inv = 1.f / l_s[ty * 8 + i];
        #pragma unroll
        for (int j = 0; j < 4; j++) {
            ctx[(size_t)(b * S_ + s) * D_ + h * DK_ + tx * 4 + j] = oacc[i][j] * inv;
        }
    }
}

// ---------------- launch ----------------------------------------------------------
extern "C" void kernel_launch(void* const* d_in, const int* in_sizes, int n_in,
                              void* d_out, int out_size) {
    const float* x  = (const float*)d_in[0];
    // d_in[1] = src_mask (no-op in reference, ignored)
    const float* Wq = (const float*)d_in[2];
    const float* bq = (const float*)d_in[3];
    const float* Wk = (const float*)d_in[4];
    const float* bk = (const float*)d_in[5];
    const float* Wv = (const float*)d_in[6];
    const float* bv = (const float*)d_in[7];
    const float* Wo = (const float*)d_in[8];
    const float* bo = (const float*)d_in[9];
    const float* W1 = (const float*)d_in[10];
    const float* b1 = (const float*)d_in[11];
    const float* W2 = (const float*)d_in[12];
    const float* b2 = (const float*)d_in[13];
    const float* a1 = (const float*)d_in[14];
    const float* g1 = (const float*)d_in[15];
    const float* a2 = (const float*)d_in[16];
    const float* g2 = (const float*)d_in[17];
    float* out = (float*)d_out;

    float *hbuf, *qb, *kb, *vb, *ctx, *x2, *ffb;
    cudaGetSymbolAddress((void**)&hbuf, g_h);
    cudaGetSymbolAddress((void**)&qb,   g_q);
    cudaGetSymbolAddress((void**)&kb,   g_k);
    cudaGetSymbolAddress((void**)&vb,   g_v);
    cudaGetSymbolAddress((void**)&ctx,  g_ctx);
    cudaGetSymbolAddress((void**)&x2,   g_x2);
    cudaGetSymbolAddress((void**)&ffb,  g_ff);

    const int FA_SMEM = FA_SMEM_FLOATS * (int)sizeof(float);
    cudaFuncSetAttribute(flash_attn_kernel,
                         cudaFuncAttributeMaxDynamicSharedMemorySize, FA_SMEM);
    cudaFuncSetAttribute(gemm_tf32<0>, cudaFuncAttributeMaxDynamicSharedMemorySize, G_SMEM_BYTES);
    cudaFuncSetAttribute(gemm_tf32<1>, cudaFuncAttributeMaxDynamicSharedMemorySize, G_SMEM_BYTES);
    cudaFuncSetAttribute(gemm_tf32<2>, cudaFuncAttributeMaxDynamicSharedMemorySize, G_SMEM_BYTES);
    cudaFuncSetAttribute(gemm_tf32<3>, cudaFuncAttributeMaxDynamicSharedMemorySize, G_SMEM_BYTES);

    dim3 gD(D_ / GBN, M_ / GBM);     // (8, 32)
    dim3 gF(DFF_ / GBN, M_ / GBM);   // (32, 32)

    // 1. LN1
    layernorm_kernel<<<M_, 256>>>(x, a1, g1, hbuf);
    // 2. QKV projections (permuted store into (b,h,s,d))
    gemm_tf32<3><<<gD, 256, G_SMEM_BYTES>>>(hbuf, Wq, bq, nullptr, qb, M_, D_, D_);
    gemm_tf32<3><<<gD, 256, G_SMEM_BYTES>>>(hbuf, Wk, bk, nullptr, kb, M_, D_, D_);
    gemm_tf32<3><<<gD, 256, G_SMEM_BYTES>>>(hbuf, Wv, bv, nullptr, vb, M_, D_, D_);
    // 3. attention
    flash_attn_kernel<<<dim3(S_ / 128, B_ * H_), 256, FA_SMEM>>>(qb, kb, vb, ctx);
    // 4. O projection + residual 1
    gemm_tf32<2><<<gD, 256, G_SMEM_BYTES>>>(ctx, Wo, bo, x, x2, M_, D_, D_);
    // 5. LN2
    layernorm_kernel<<<M_, 256>>>(x2, a2, g2, hbuf);
    // 6. FFN up + ReLU
    gemm_tf32<1><<<gF, 256, G_SMEM_BYTES>>>(hbuf, W1, b1, nullptr, ffb, M_, DFF_, D_);
    // 7. FFN down + residual 2 -> output
    gemm_tf32<2><<<gD, 256, G_SMEM_BYTES>>>(ffb, W2, b2, x2, out, M_, D_, DFF_);
}

// round 5
// speedup vs baseline: 2.7538x; 1.3773x over previous
#include <cuda_runtime.h>
#include <cstdint>
#include <stdint.h>
#include <math.h>

#define B_   2
#define S_   2048
#define D_   1024
#define H_   16
#define DK_  64
#define DFF_ 4096
#define M_   (B_ * S_)      // 4096 rows
#define EPS_ 1e-6f

// ---------------- scratch (device globals; no allocation allowed) ----------------
__device__ float g_h  [(size_t)M_ * D_];    // LN output (reused for LN2)
__device__ float g_q  [(size_t)M_ * D_];    // (b,h,s,d) layout
__device__ float g_k  [(size_t)M_ * D_];
__device__ float g_v  [(size_t)M_ * D_];
__device__ float g_ctx[(size_t)M_ * D_];    // (m, h*DK+d) layout
__device__ float g_x2 [(size_t)M_ * D_];    // residual-1 output
__device__ float g_ff [(size_t)M_ * DFF_];  // relu(h2@W1+b1)
// transposed weights: WqT,WkT,WvT,WoT (D*D each), W1T (DFF*D), W2T (D*DFF)
__device__ float g_wt [(size_t)4 * D_ * D_ + 2 * (size_t)D_ * DFF_];

// ---------------- weight transpose: WT[n][k] = W[k][n] ---------------------------
__global__ void transpose_kernel(const float* __restrict__ W, float* __restrict__ WT,
                                 int K, int N) {
    __shared__ float tile[32][33];
    int k0 = blockIdx.y * 32, n0 = blockIdx.x * 32;
    int tx = threadIdx.x, ty = threadIdx.y;        // (32, 8)
    #pragma unroll
    for (int i = 0; i < 4; i++)
        tile[ty + i * 8][tx] = W[(size_t)(k0 + ty + i * 8) * N + n0 + tx];
    __syncthreads();
    #pragma unroll
    for (int i = 0; i < 4; i++)
        WT[(size_t)(n0 + ty + i * 8) * K + k0 + tx] = tile[tx][ty + i * 8];
}

// ---------------- layernorm: alpha*(x-mean)/(std+eps)+beta, std unbiased ----------
__global__ void layernorm_kernel(const float* __restrict__ x,
                                 const float* __restrict__ alpha,
                                 const float* __restrict__ beta,
                                 float* __restrict__ out) {
    int row = blockIdx.x;
    int t = threadIdx.x;                       // 256 threads, 4 elems each (D=1024)
    const float4* xr = (const float4*)(x + (size_t)row * D_);
    float4 v = xr[t];
    float s  = v.x + v.y + v.z + v.w;
    float sq = v.x*v.x + v.y*v.y + v.z*v.z + v.w*v.w;
    #pragma unroll
    for (int o = 16; o > 0; o >>= 1) {
        s  += __shfl_xor_sync(0xFFFFFFFFu, s,  o);
        sq += __shfl_xor_sync(0xFFFFFFFFu, sq, o);
    }
    __shared__ float ss[8], sqs[8];
    __shared__ float mean_sh, inv_sh;
    int w = t >> 5;
    if ((t & 31) == 0) { ss[w] = s; sqs[w] = sq; }
    __syncthreads();
    if (t == 0) {
        float S = 0.f, SQ = 0.f;
        #pragma unroll
        for (int i = 0; i < 8; i++) { S += ss[i]; SQ += sqs[i]; }
        float mean = S / (float)D_;
        float var  = (SQ - (float)D_ * mean * mean) / (float)(D_ - 1);
        float sd   = sqrtf(fmaxf(var, 0.f));
        mean_sh = mean;
        inv_sh  = 1.f / (sd + EPS_);
    }
    __syncthreads();
    float a = alpha[0], g = beta[0];
    float mean = mean_sh, inv = inv_sh;
    float4 o4;
    o4.x = a * (v.x - mean) * inv + g;
    o4.y = a * (v.y - mean) * inv + g;
    o4.z = a * (v.z - mean) * inv + g;
    o4.w = a * (v.w - mean) * inv + g;
    ((float4*)(out + (size_t)row * D_))[t] = o4;
}

// ======================= TF32 tensor-core GEMM ===================================
// C = A(MxK) @ B(KxN) + bias, with B supplied TRANSPOSED: BT is [N][K] row-major.
// EPI: 0 = bias, 1 = bias+relu, 2 = bias+residual add, 3 = bias + QKV permute store
// Block tile 128x128, BK=32, 8 warps (each 32x64), 3-stage cp.async pipeline.
// Fragments use a k-permutation (slot tig <-> phys 2*tig, slot tig+4 <-> 2*tig+1)
// applied identically to A and B, enabling LDS.64 operand loads. Raw fp32 bits
// are fed to the tf32 mma (HW truncates low mantissa bits) -> no cvt on ALU pipe.

#define GBM 128
#define GBN 128
#define GBK 32
#define G_STR 36                       // 36 mod 32 == 4 -> conflict-friendly
#define G_TSZ (128 * G_STR)            // 4608 floats per tile
#define G_STG (2 * G_TSZ)              // A + BT per stage
#define G_STAGES 3
#define G_SMEM_BYTES (G_STAGES * G_STG * 4)   // 110592 B

__device__ __forceinline__ uint32_t fb(float f) { return __float_as_uint(f); }

__device__ __forceinline__ void mma_tf32(float c[4], const uint32_t a[4],
                                         uint32_t b0, uint32_t b1) {
    asm volatile(
        "mma.sync.aligned.m16n8k8.row.col.f32.tf32.tf32.f32 "
        "{%0,%1,%2,%3}, {%4,%5,%6,%7}, {%8,%9}, {%0,%1,%2,%3};"
        : "+f"(c[0]), "+f"(c[1]), "+f"(c[2]), "+f"(c[3])
        : "r"(a[0]), "r"(a[1]), "r"(a[2]), "r"(a[3]), "r"(b0), "r"(b1));
}

__device__ __forceinline__ void cp16(void* smem_dst, const void* gsrc) {
    uint32_t s = (uint32_t)__cvta_generic_to_shared(smem_dst);
    asm volatile("cp.async.cg.shared.global [%0], [%1], 16;\n" :: "r"(s), "l"(gsrc));
}

template<int EPI>
__global__ void __launch_bounds__(256)
gemm_tf32(const float* __restrict__ A,
          const float* __restrict__ BT,
          const float* __restrict__ bias,
          const float* __restrict__ res,
          float* __restrict__ C,
          int Mdim, int Ndim, int Kdim) {
    extern __shared__ float sm[];

    int bx = blockIdx.x, by = blockIdx.y;
    int t = threadIdx.x;
    int lane = t & 31, warp = t >> 5;
    int wm = warp >> 1;                // 0..3 -> 32-row strips
    int wn = warp & 1;                 // 0..1 -> 64-col strips
    int gid = lane >> 2, tig = lane & 3;

    const int nk = Kdim / GBK;

    // prefetch one stage: A tile [128][32] rows by*128.., BT tile [128][32] rows bx*128..
    auto prefetch = [&](int stage, int k0) {
        float* abase = sm + stage * G_STG;
        float* bbase = abase + G_TSZ;
        #pragma unroll
        for (int i = 0; i < 4; i++) {
            int lin = t + i * 256;                     // 0..1023
            int m = lin >> 3, ch = (lin & 7) * 4;      // 8 x 16B chunks per row
            cp16(abase + m * G_STR + ch,
                 A + (size_t)(by * GBM + m) * Kdim + k0 + ch);
            cp16(bbase + m * G_STR + ch,
                 BT + (size_t)(bx * GBN + m) * Kdim + k0 + ch);
        }
    };

    float acc[2][8][4];
    #pragma unroll
    for (int mt = 0; mt < 2; mt++)
        #pragma unroll
        for (int nt = 0; nt < 8; nt++)
            #pragma unroll
            for (int c = 0; c < 4; c++) acc[mt][nt][c] = 0.f;

    #pragma unroll
    for (int s = 0; s < G_STAGES; s++) {
        prefetch(s, s * GBK);
        asm volatile("cp.async.commit_group;" ::: "memory");
    }

    for (int kt = 0; kt < nk; kt++) {
        asm volatile("cp.async.wait_group 2;" ::: "memory");
        __syncthreads();

        const float* pA = sm + (kt % G_STAGES) * G_STG;
        const float* pB = pA + G_TSZ;

        #pragma unroll
        for (int k8 = 0; k8 < 4; k8++) {
            int kc = k8 * 8 + 2 * tig;
            uint32_t a[2][4];
            #pragma unroll
            for (int mt = 0; mt < 2; mt++) {
                int r0 = wm * 32 + mt * 16;
                float2 a0 = *(const float2*)(pA + (r0 + gid    ) * G_STR + kc);
                float2 a1 = *(const float2*)(pA + (r0 + gid + 8) * G_STR + kc);
                a[mt][0] = fb(a0.x); a[mt][1] = fb(a1.x);
                a[mt][2] = fb(a0.y); a[mt][3] = fb(a1.y);
            }
            #pragma unroll
            for (int nt = 0; nt < 8; nt++) {
                int n0 = wn * 64 + nt * 8;
                float2 bv = *(const float2*)(pB + (n0 + gid) * G_STR + kc);
                uint32_t b0 = fb(bv.x), b1 = fb(bv.y);
                mma_tf32(acc[0][nt], a[0], b0, b1);
                mma_tf32(acc[1][nt], a[1], b0, b1);
            }
        }

        __syncthreads();
        if (kt + G_STAGES < nk) prefetch((kt % G_STAGES), (kt + G_STAGES) * GBK);
        asm volatile("cp.async.commit_group;" ::: "memory");
    }

    // epilogue
    auto store2 = [&](int row, int col, float vx, float vy) {
        vx += bias[col];
        vy += bias[col + 1];
        if (EPI == 1) { vx = fmaxf(vx, 0.f); vy = fmaxf(vy, 0.f); }
        if (EPI == 2) {
            float2 r = *(const float2*)(res + (size_t)row * Ndim + col);
            vx += r.x; vy += r.y;
        }
        if (EPI == 3) {
            int bb = row / S_, s = row % S_;
            int hh = col >> 6, dd = col & 63;
            float2* p = (float2*)(C + ((((size_t)bb * H_ + hh) * S_) + s) * DK_ + dd);
            *p = make_float2(vx, vy);
        } else {
            *(float2*)(C + (size_t)row * Ndim + col) = make_float2(vx, vy);
        }
    };

    #pragma unroll
    for (int mt = 0; mt < 2; mt++) {
        #pragma unroll
        for (int nt = 0; nt < 8; nt++) {
            int row = by * GBM + wm * 32 + mt * 16 + gid;
            int col = bx * GBN + wn * 64 + nt * 8 + tig * 2;
            store2(row,     col, acc[mt][nt][0], acc[mt][nt][1]);
            store2(row + 8, col, acc[mt][nt][2], acc[mt][nt][3]);
        }
    }
}

// ================= flash attention, TF32 mma + register softmax ==================
// grid: (S/128, B*H), block 256 (8 warps). Each warp owns 16 q-rows x all 64 dims.
// KV tile = 64 keys. smem strides 68 (68 mod 32 == 4).
#define FA_STR 68
#define FA_SMEM_BYTES ((128*FA_STR + 64*FA_STR + 64*FA_STR + 128*FA_STR) * 4)  // 104448

__global__ void __launch_bounds__(256)
flash_attn_mma(const float* __restrict__ Q,
               const float* __restrict__ K,
               const float* __restrict__ V,
               float* __restrict__ ctx) {
    extern __shared__ float sm[];
    float* smQ  = sm;                       // [128][68] q-rows x dims (pre-scaled)
    float* smK  = smQ  + 128 * FA_STR;      // [64][68]  keys x dims
    float* smVT = smK  +  64 * FA_STR;      // [64][68]  dims x keys (V^T)
    float* smP  = smVT +  64 * FA_STR;      // [128][68] q-rows x keys (warp-private rows)

    int tid = threadIdx.x;
    int lane = tid & 31, wq = tid >> 5;
    int gid = lane >> 2, tig = lane & 3;
    int bh = blockIdx.y, qt = blockIdx.x;
    int qr = wq * 16;

    const float* Qp = Q + ((size_t)bh * S_ + qt * 128) * DK_;
    const float* Kp = K + (size_t)bh * S_ * DK_;
    const float* Vp = V + (size_t)bh * S_ * DK_;

    // Q tile, scaled by 1/sqrt(dk) = 0.125
    for (int idx = tid; idx < 128 * 16; idx += 256) {
        int r = idx >> 4, c4 = (idx & 15) * 4;
        float4 v = *(const float4*)(Qp + (size_t)r * DK_ + c4);
        v.x *= 0.125f; v.y *= 0.125f; v.z *= 0.125f; v.w *= 0.125f;
        *(float4*)(smQ + r * FA_STR + c4) = v;
    }

    float m0 = -1e30f, m1 = -1e30f, l0 = 0.f, l1 = 0.f;
    float o[8][4];
    #pragma unroll
    for (int nt = 0; nt < 8; nt++)
        #pragma unroll
        for (int c = 0; c < 4; c++) o[nt][c] = 0.f;

    for (int kt = 0; kt < S_ / 64; kt++) {
        __syncthreads();
        const float* Kt = Kp + (size_t)kt * 64 * DK_;
        const float* Vt = Vp + (size_t)kt * 64 * DK_;
        for (int idx = tid; idx < 64 * 16; idx += 256) {
            int r = idx >> 4, c4 = (idx & 15) * 4;
            *(float4*)(smK + r * FA_STR + c4) = *(const float4*)(Kt + (size_t)r * DK_ + c4);
            float4 vv = *(const float4*)(Vt + (size_t)r * DK_ + c4);
            smVT[(c4 + 0) * FA_STR + r] = vv.x;
            smVT[(c4 + 1) * FA_STR + r] = vv.y;
            smVT[(c4 + 2) * FA_STR + r] = vv.z;
            smVT[(c4 + 3) * FA_STR + r] = vv.w;
        }
        __syncthreads();

        // ---- S = Q @ K^T  (M=16 rows, N=64 keys, K=64 dims) ----
        float sacc[8][4];
        #pragma unroll
        for (int nt = 0; nt < 8; nt++)
            #pragma unroll
            for (int c = 0; c < 4; c++) sacc[nt][c] = 0.f;
        #pragma unroll
        for (int kk = 0; kk < 8; kk++) {
            int kc = kk * 8 + 2 * tig;
            uint32_t a[4];
            float2 a0 = *(const float2*)(smQ + (qr + gid    ) * FA_STR + kc);
            float2 a1 = *(const float2*)(smQ + (qr + gid + 8) * FA_STR + kc);
            a[0] = fb(a0.x); a[1] = fb(a1.x); a[2] = fb(a0.y); a[3] = fb(a1.y);
            #pragma unroll
            for (int nt = 0; nt < 8; nt++) {
                float2 bv = *(const float2*)(smK + (nt * 8 + gid) * FA_STR + kc);
                mma_tf32(sacc[nt], a, fb(bv.x), fb(bv.y));
            }
        }

        // ---- online softmax in registers (rows gid and gid+8 of warp tile) ----
        float tmx0 = -1e30f, tmx1 = -1e30f;
        #pragma unroll
        for (int nt = 0; nt < 8; nt++) {
            tmx0 = fmaxf(tmx0, fmaxf(sacc[nt][0], sacc[nt][1]));
            tmx1 = fmaxf(tmx1, fmaxf(sacc[nt][2], sacc[nt][3]));
        }
        tmx0 = fmaxf(tmx0, __shfl_xor_sync(0xFFFFFFFFu, tmx0, 1));
        tmx0 = fmaxf(tmx0, __shfl_xor_sync(0xFFFFFFFFu, tmx0, 2));
        tmx1 = fmaxf(tmx1, __shfl_xor_sync(0xFFFFFFFFu, tmx1, 1));
        tmx1 = fmaxf(tmx1, __shfl_xor_sync(0xFFFFFFFFu, tmx1, 2));
        float nm0 = fmaxf(m0, tmx0), nm1 = fmaxf(m1, tmx1);
        float sum0 = 0.f, sum1 = 0.f;
        #pragma unroll
        for (int nt = 0; nt < 8; nt++) {
            sacc[nt][0] = __expf(sacc[nt][0] - nm0);
            sacc[nt][1] = __expf(sacc[nt][1] - nm0);
            sacc[nt][2] = __expf(sacc[nt][2] - nm1);
            sacc[nt][3] = __expf(sacc[nt][3] - nm1);
            sum0 += sacc[nt][0] + sacc[nt][1];
            sum1 += sacc[nt][2] + sacc[nt][3];
        }
        sum0 += __shfl_xor_sync(0xFFFFFFFFu, sum0, 1);
        sum0 += __shfl_xor_sync(0xFFFFFFFFu, sum0, 2);
        sum1 += __shfl_xor_sync(0xFFFFFFFFu, sum1, 1);
        sum1 += __shfl_xor_sync(0xFFFFFFFFu, sum1, 2);
        float rf0 = __expf(m0 - nm0), rf1 = __expf(m1 - nm1);
        m0 = nm0; m1 = nm1;
        l0 = l0 * rf0 + sum0;
        l1 = l1 * rf1 + sum1;
        #pragma unroll
        for (int nt = 0; nt < 8; nt++) {
            o[nt][0] *= rf0; o[nt][1] *= rf0;
            o[nt][2] *= rf1; o[nt][3] *= rf1;
        }
        // P -> warp-private smem rows
        #pragma unroll
        for (int nt = 0; nt < 8; nt++) {
            *(float2*)(smP + (qr + gid    ) * FA_STR + nt * 8 + tig * 2)
                = make_float2(sacc[nt][0], sacc[nt][1]);
            *(float2*)(smP + (qr + gid + 8) * FA_STR + nt * 8 + tig * 2)
                = make_float2(sacc[nt][2], sacc[nt][3]);
        }
        __syncwarp();

        // ---- O += P @ V  (M=16 rows, N=64 dims, K=64 keys) ----
        #pragma unroll
        for (int kk = 0; kk < 8; kk++) {
            int kc = kk * 8 + 2 * tig;
            uint32_t a[4];
            float2 p0 = *(const float2*)(smP + (qr + gid    ) * FA_STR + kc);
            float2 p1 = *(const float2*)(smP + (qr + gid + 8) * FA_STR + kc);
            a[0] = fb(p0.x); a[1] = fb(p1.x); a[2] = fb(p0.y); a[3] = fb(p1.y);
            #pragma unroll
            for (int nt = 0; nt < 8; nt++) {
                float2 bv = *(const float2*)(smVT + (nt * 8 + gid) * FA_STR + kc);
                mma_tf32(o[nt], a, fb(bv.x), fb(bv.y));
            }
        }
    }

    float inv0 = 1.f / l0, inv1 = 1.f / l1;
    int b = bh >> 4, h = bh & 15;
    int s0 = qt * 128 + qr + gid;
    #pragma unroll
    for (int nt = 0; nt < 8; nt++) {
        int col = h * DK_ + nt * 8 + tig * 2;
        *(float2*)(ctx + (size_t)(b * S_ + s0    ) * D_ + col)
            = make_float2(o[nt][0] * inv0, o[nt][1] * inv0);
        *(float2*)(ctx + (size_t)(b * S_ + s0 + 8) * D_ + col)
            = make_float2(o[nt][2] * inv1, o[nt][3] * inv1);
    }
}

// ---------------- launch ----------------------------------------------------------
extern "C" void kernel_launch(void* const* d_in, const int* in_sizes, int n_in,
                              void* d_out, int out_size) {
    const float* x  = (const float*)d_in[0];
    // d_in[1] = src_mask (no-op in reference, ignored)
    const float* Wq = (const float*)d_in[2];
    const float* bq = (const float*)d_in[3];
    const float* Wk = (const float*)d_in[4];
    const float* bk = (const float*)d_in[5];
    const float* Wv = (const float*)d_in[6];
    const float* bv = (const float*)d_in[7];
    const float* Wo = (const float*)d_in[8];
    const float* bo = (const float*)d_in[9];
    const float* W1 = (const float*)d_in[10];
    const float* b1 = (const float*)d_in[11];
    const float* W2 = (const float*)d_in[12];
    const float* b2 = (const float*)d_in[13];
    const float* a1 = (const float*)d_in[14];
    const float* g1 = (const float*)d_in[15];
    const float* a2 = (const float*)d_in[16];
    const float* g2 = (const float*)d_in[17];
    float* out = (float*)d_out;

    float *hbuf, *qb, *kb, *vb, *ctx, *x2, *ffb, *wt;
    cudaGetSymbolAddress((void**)&hbuf, g_h);
    cudaGetSymbolAddress((void**)&qb,   g_q);
    cudaGetSymbolAddress((void**)&kb,   g_k);
    cudaGetSymbolAddress((void**)&vb,   g_v);
    cudaGetSymbolAddress((void**)&ctx,  g_ctx);
    cudaGetSymbolAddress((void**)&x2,   g_x2);
    cudaGetSymbolAddress((void**)&ffb,  g_ff);
    cudaGetSymbolAddress((void**)&wt,   g_wt);

    float* WqT = wt;
    float* WkT = WqT + (size_t)D_ * D_;
    float* WvT = WkT + (size_t)D_ * D_;
    float* WoT = WvT + (size_t)D_ * D_;
    float* W1T = WoT + (size_t)D_ * D_;              // [DFF][D]
    float* W2T = W1T + (size_t)D_ * DFF_;            // [D][DFF]

    cudaFuncSetAttribute(flash_attn_mma,
                         cudaFuncAttributeMaxDynamicSharedMemorySize, FA_SMEM_BYTES);
    cudaFuncSetAttribute(gemm_tf32<0>, cudaFuncAttributeMaxDynamicSharedMemorySize, G_SMEM_BYTES);
    cudaFuncSetAttribute(gemm_tf32<1>, cudaFuncAttributeMaxDynamicSharedMemorySize, G_SMEM_BYTES);
    cudaFuncSetAttribute(gemm_tf32<2>, cudaFuncAttributeMaxDynamicSharedMemorySize, G_SMEM_BYTES);
    cudaFuncSetAttribute(gemm_tf32<3>, cudaFuncAttributeMaxDynamicSharedMemorySize, G_SMEM_BYTES);

    dim3 tb(32, 8);
    // 0. weight transposes (inputs only -> can run first, every replay)
    transpose_kernel<<<dim3(D_/32,  D_/32),  tb>>>(Wq, WqT, D_, D_);
    transpose_kernel<<<dim3(D_/32,  D_/32),  tb>>>(Wk, WkT, D_, D_);
    transpose_kernel<<<dim3(D_/32,  D_/32),  tb>>>(Wv, WvT, D_, D_);
    transpose_kernel<<<dim3(D_/32,  D_/32),  tb>>>(Wo, WoT, D_, D_);
    transpose_kernel<<<dim3(DFF_/32, D_/32), tb>>>(W1, W1T, D_, DFF_);
    transpose_kernel<<<dim3(D_/32, DFF_/32), tb>>>(W2, W2T, DFF_, D_);

    dim3 gD(D_ / GBN, M_ / GBM);     // (8, 32)
    dim3 gF(DFF_ / GBN, M_ / GBM);   // (32, 32)

    // 1. LN1
    layernorm_kernel<<<M_, 256>>>(x, a1, g1, hbuf);
    // 2. QKV projections (permuted store into (b,h,s,d))
    gemm_tf32<3><<<gD, 256, G_SMEM_BYTES>>>(hbuf, WqT, bq, nullptr, qb, M_, D_, D_);
    gemm_tf32<3><<<gD, 256, G_SMEM_BYTES>>>(hbuf, WkT, bk, nullptr, kb, M_, D_, D_);
    gemm_tf32<3><<<gD, 256, G_SMEM_BYTES>>>(hbuf, WvT, bv, nullptr, vb, M_, D_, D_);
    // 3. attention (tensor-core)
    flash_attn_mma<<<dim3(S_ / 128, B_ * H_), 256, FA_SMEM_BYTES>>>(qb, kb, vb, ctx);
    // 4. O projection + residual 1
    gemm_tf32<2><<<gD, 256, G_SMEM_BYTES>>>(ctx, WoT, bo, x, x2, M_, D_, D_);
    // 5. LN2
    layernorm_kernel<<<M_, 256>>>(x2, a2, g2, hbuf);
    // 6. FFN up + ReLU
    gemm_tf32<1><<<gF, 256, G_SMEM_BYTES>>>(hbuf, W1T, b1, nullptr, ffb, M_, DFF_, D_);
    // 7. FFN down + residual 2 -> output
    gemm_tf32<2><<<gD, 256, G_SMEM_BYTES>>>(ffb, W2T, b2, x2, out, M_, D_, DFF_);
}